// round 2
// baseline (speedup 1.0000x reference)
#include <cuda_runtime.h>
#include <stdint.h>

#define BATCH 64
#define INSZ 1024
#define KSZ 1025          // inputs + bias neuron
#define MSZ 1024
#define MAX_SPIKE 100000.0f
#define EPSV 1e-10f

// Scratch (no allocations allowed): sorted spike times, gaps, and W row offsets.
__device__ float g_xs[BATCH][KSZ];
__device__ float g_dx[BATCH][KSZ];
__device__ int   g_row[BATCH][KSZ];

// ---------------------------------------------------------------------------
// Kernel 1: per-batch bitonic sort of (spike time, index), padded to 2048.
// Keys are positive floats -> monotone as uint32. Index packed in low 32 bits
// makes the sort stable (matches jnp.argsort tie behavior).
// ---------------------------------------------------------------------------
__global__ void __launch_bounds__(1024) snn_sort_kernel(const float* __restrict__ X) {
    __shared__ unsigned long long s[2048];
    const int b = blockIdx.x;
    const int t = threadIdx.x;

    for (int i = t; i < 2048; i += 1024) {
        unsigned long long v;
        if (i < INSZ) {
            v = ((unsigned long long)__float_as_uint(X[b * INSZ + i]) << 32) | (unsigned)i;
        } else if (i == INSZ) {
            // bias neuron fires at t = 1.0, weight row INSZ (zeros)
            v = ((unsigned long long)__float_as_uint(1.0f) << 32) | (unsigned)INSZ;
        } else {
            v = ~0ull;  // +inf padding, sorts last
        }
        s[i] = v;
    }
    __syncthreads();

    for (int size = 2; size <= 2048; size <<= 1) {
        for (int stride = size >> 1; stride > 0; stride >>= 1) {
            const int lo = ((t & ~(stride - 1)) << 1) | (t & (stride - 1));
            const int hi = lo + stride;
            const unsigned long long a = s[lo], c = s[hi];
            const bool up = (lo & size) == 0;
            if ((a > c) == up) { s[lo] = c; s[hi] = a; }
            __syncthreads();
        }
    }

    for (int i = t; i < KSZ; i += 1024) {
        const unsigned long long v = s[i];
        const float x  = __uint_as_float((unsigned)(v >> 32));
        const float xn = (i + 1 < KSZ) ? __uint_as_float((unsigned)(s[i + 1] >> 32))
                                       : MAX_SPIKE;
        g_xs[b][i]  = x;
        g_dx[b][i]  = xn - x;
        g_row[b][i] = ((int)(v & 0xffffffffu)) * MSZ;
    }
}

// ---------------------------------------------------------------------------
// Kernel 2: margin-recurrence scan.
//   cwp_k = cw_k - 1     (running weight sum minus threshold)
//   G_k   = cwp_k * x_k - cwt_k,   G_{k+1} = G_k + cwp_k * dx_k   (one FMA)
// Window k is valid iff  G_k <= 0 && G_{k+1} >= 0 && cwp_k >= eps.
// First valid window gives the answer: T = x_k - G_k / cwp_k.
// Each thread owns 2 adjacent output columns (coalesced float2 loads of W rows).
// Grid: (MSZ/256, BATCH), 128 threads.
// ---------------------------------------------------------------------------
__global__ void __launch_bounds__(128, 8) snn_scan_kernel(
    const float* __restrict__ W, float* __restrict__ out)
{
    __shared__ float s_xs[KSZ];
    __shared__ float s_dx[KSZ];
    __shared__ int   s_row[KSZ];

    const int b = blockIdx.y;
    const int t = threadIdx.x;

    for (int i = t; i < KSZ; i += 128) {
        s_xs[i]  = g_xs[b][i];
        s_dx[i]  = g_dx[b][i];
        s_row[i] = g_row[b][i];
    }
    __syncthreads();

    const int m = blockIdx.x * 256 + t * 2;
    const float* Wm = W + m;

    const float x0 = s_xs[0];
    float cwp0 = -1.0f, cwp1 = -1.0f;   // cw - THRESHOLD, starts at -1
    float G0 = -x0, G1 = -x0;           // G_0 = -x_0 (independent of w_0)
    float Gf0 = 0.f, Gf1 = 0.f;
    float cf0 = 1.f, cf1 = 1.f;
    int   kf0 = 0,   kf1 = 0;
    bool  done0 = false, done1 = false;

    #pragma unroll 1
    for (int k = 0; k < KSZ - 1; k += 8) {
        #pragma unroll
        for (int u = 0; u < 8; u++) {
            const int kk = k + u;
            const float2 w  = *reinterpret_cast<const float2*>(Wm + s_row[kk]);
            const float dxk = s_dx[kk];
            cwp0 += w.x;
            cwp1 += w.y;
            const float Gn0 = fmaf(cwp0, dxk, G0);
            const float Gn1 = fmaf(cwp1, dxk, G1);
            if (!done0 && G0 <= 0.f && Gn0 >= 0.f && cwp0 >= EPSV) {
                Gf0 = G0; cf0 = cwp0; kf0 = kk; done0 = true;
            }
            if (!done1 && G1 <= 0.f && Gn1 >= 0.f && cwp1 >= EPSV) {
                Gf1 = G1; cf1 = cwp1; kf1 = kk; done1 = true;
            }
            G0 = Gn0; G1 = Gn1;
        }
        if (__all_sync(0xffffffffu, done0 && done1)) break;
    }

    // Tail element k = KSZ-1 (its window extends to MAX_SPIKE via g_dx).
    // Safe even after early break: all lanes were done, guards block updates.
    {
        const int kk = KSZ - 1;
        const float2 w  = *reinterpret_cast<const float2*>(Wm + s_row[kk]);
        const float dxk = s_dx[kk];
        cwp0 += w.x;
        cwp1 += w.y;
        const float Gn0 = fmaf(cwp0, dxk, G0);
        const float Gn1 = fmaf(cwp1, dxk, G1);
        if (!done0 && G0 <= 0.f && Gn0 >= 0.f && cwp0 >= EPSV) {
            Gf0 = G0; cf0 = cwp0; kf0 = kk; done0 = true;
        }
        if (!done1 && G1 <= 0.f && Gn1 >= 0.f && cwp1 >= EPSV) {
            Gf1 = G1; cf1 = cwp1; kf1 = kk; done1 = true;
        }
    }

    const float r0 = done0 ? (s_xs[kf0] - Gf0 / cf0) : MAX_SPIKE;
    const float r1 = done1 ? (s_xs[kf1] - Gf1 / cf1) : MAX_SPIKE;
    out[(size_t)b * MSZ + m]     = r0;
    out[(size_t)b * MSZ + m + 1] = r1;
}

// ---------------------------------------------------------------------------
extern "C" void kernel_launch(void* const* d_in, const int* in_sizes, int n_in,
                              void* d_out, int out_size) {
    const float* X = (const float*)d_in[0];   // [64, 1024] spike times
    const float* W = (const float*)d_in[1];   // [1025, 1024] weights
    float* out = (float*)d_out;               // [64, 1024]

    snn_sort_kernel<<<BATCH, 1024>>>(X);
    snn_scan_kernel<<<dim3(MSZ / 256, BATCH), 128>>>(W, out);
}

// round 4
// speedup vs baseline: 1.4320x; 1.4320x over previous
#include <cuda_runtime.h>
#include <stdint.h>

#define BATCH 64
#define INSZ 1024
#define KSZ 1025          // inputs + bias neuron (bias always first: t=1.0 <= X)
#define MSZ 1024
#define MAX_SPIKE 100000.0f

// Scratch: per batch, sorted (dx, row-byte-offset) pairs and sorted spike times.
__device__ float2 g_pack[BATCH][KSZ];   // .x = dx_k, .y = int_bits(row_k * 4096)
__device__ float  g_xs[BATCH][KSZ];

// ---------------------------------------------------------------------------
// Kernel 1: per-batch bitonic sort of the 1024 X values (bias hardcoded at
// slot 0 since bias=1.0 <= min X; tie order is provably irrelevant).
// Each of 1024 threads holds one (x, idx) packed u64. Strides <=16 run in
// registers via shfl_xor; strides >=32 via shared memory.
// ---------------------------------------------------------------------------
__global__ void __launch_bounds__(1024) snn_sort_kernel(const float* __restrict__ X) {
    __shared__ unsigned long long sh[1024];
    __shared__ float sx[1025];
    const int b = blockIdx.x;
    const int t = threadIdx.x;

    unsigned long long v =
        ((unsigned long long)__float_as_uint(X[b * INSZ + t]) << 32) | (unsigned)t;

    #pragma unroll 1
    for (int size = 2; size <= 1024; size <<= 1) {
        // cross-warp strides via shared memory
        #pragma unroll 1
        for (int stride = size >> 1; stride >= 32; stride >>= 1) {
            sh[t] = v;
            __syncthreads();
            const unsigned long long u = sh[t ^ stride];
            __syncthreads();
            const bool dir = (t & size) != 0;
            const bool keepmin = (((t & stride) == 0) != dir);
            v = keepmin ? (v < u ? v : u) : (v < u ? u : v);
        }
        // in-warp strides via shuffle
        const int s0 = (size >> 1) < 16 ? (size >> 1) : 16;
        #pragma unroll 1
        for (int stride = s0; stride >= 1; stride >>= 1) {
            const unsigned long long u = __shfl_xor_sync(0xffffffffu, v, stride);
            const bool dir = (t & size) != 0;
            const bool keepmin = (((t & stride) == 0) != dir);
            v = keepmin ? (v < u ? v : u) : (v < u ? u : v);
        }
    }

    // sorted X element t goes to slot t+1; bias at slot 0
    sx[t + 1] = __uint_as_float((unsigned)(v >> 32));
    if (t == 0) sx[0] = 1.0f;
    __syncthreads();

    const int row = (int)(v & 0xffffffffu);     // original X index
    const int s = t + 1;
    const float x  = sx[s];
    const float xn = (s == KSZ - 1) ? MAX_SPIKE : sx[s + 1];
    g_xs[b][s]   = x;
    g_pack[b][s] = make_float2(xn - x, __int_as_float(row * (MSZ * 4)));
    if (t == 0) {
        g_xs[b][0]   = 1.0f;
        g_pack[b][0] = make_float2(sx[1] - 1.0f, __int_as_float(INSZ * (MSZ * 4)));
    }
}

// ---------------------------------------------------------------------------
// Kernel 2: margin-recurrence scan, 1 output column per thread.
//   cwp_k = cw_k - 1;  G_{k+1} = G_k + cwp_k * dx_k   (G_0 = -x_0 = -1)
// First k with G_{k+1} >= 0 is the (unique first) valid window:
//   T = x_k - G_k / cwp_k.
// While not-done (nd): keep overwriting (Gf, cf, kf); last write is the
// crossing step. If nd survives the whole scan -> no spike -> MAX_SPIKE.
// Grid: (MSZ/128, BATCH), 128 threads.
// ---------------------------------------------------------------------------
__global__ void __launch_bounds__(128) snn_scan_kernel(
    const float* __restrict__ W, float* __restrict__ out)
{
    __shared__ float2 sp[KSZ];
    __shared__ float  sxs[KSZ];

    const int b = blockIdx.y;
    const int t = threadIdx.x;

    for (int i = t; i < KSZ; i += 128) {
        sp[i]  = g_pack[b][i];
        sxs[i] = g_xs[b][i];
    }
    __syncthreads();

    const int m = blockIdx.x * 128 + t;
    const char* Wb = (const char*)W + (size_t)m * 4;

    float cwp = -1.0f;          // cw - THRESHOLD
    float G   = -1.0f;          // G_0 = -x_0, x_0 = bias = 1.0
    float Gf  = 0.0f, cf = 1.0f;
    int   kf  = 0;
    bool  nd  = true;           // not done

    #pragma unroll 1
    for (int k = 0; k < KSZ - 1; k += 8) {
        #pragma unroll
        for (int u = 0; u < 8; u++) {
            const int kk = k + u;
            const float2 p = sp[kk];
            const float  w = *(const float*)(Wb + __float_as_int(p.y));
            cwp += w;
            const float Gn = fmaf(cwp, p.x, G);
            Gf = nd ? G   : Gf;
            cf = nd ? cwp : cf;
            kf = nd ? kk  : kf;
            nd = nd && (Gn < 0.0f);
            G  = Gn;
        }
    }
    {   // tail element k = KSZ-1 (window extends to MAX_SPIKE via dx)
        const int kk = KSZ - 1;
        const float2 p = sp[kk];
        const float  w = *(const float*)(Wb + __float_as_int(p.y));
        cwp += w;
        const float Gn = fmaf(cwp, p.x, G);
        Gf = nd ? G   : Gf;
        cf = nd ? cwp : cf;
        kf = nd ? kk  : kf;
        nd = nd && (Gn < 0.0f);
    }

    out[(size_t)b * MSZ + m] = nd ? MAX_SPIKE : (sxs[kf] - Gf / cf);
}

// ---------------------------------------------------------------------------
extern "C" void kernel_launch(void* const* d_in, const int* in_sizes, int n_in,
                              void* d_out, int out_size) {
    const float* X = (const float*)d_in[0];   // [64, 1024] spike times
    const float* W = (const float*)d_in[1];   // [1025, 1024] weights
    float* out = (float*)d_out;               // [64, 1024]

    snn_sort_kernel<<<BATCH, 1024>>>(X);
    snn_scan_kernel<<<dim3(MSZ / 128, BATCH), 128>>>(W, out);
}

// round 7
// speedup vs baseline: 2.0695x; 1.4452x over previous
#include <cuda_runtime.h>
#include <stdint.h>

#define BATCH 64
#define INSZ 1024
#define KSZ 1025          // inputs + bias neuron (bias always first: t=1.0 <= X)
#define KPAD 1056         // 66 chunks of 16 (padding is a provable no-op: w=0, dx=0)
#define CHUNK 16
#define NCHUNK (KPAD / CHUNK)
#define NSTAGE 4
#define MSZ 1024
#define MAX_SPIKE 100000.0f

// Scratch: per batch, sorted spike times, gaps, and W-row byte offsets.
__device__ float g_xs[BATCH][KPAD];
__device__ float g_dx[BATCH][KPAD];
__device__ int   g_row[BATCH][KPAD];

// ---------------------------------------------------------------------------
// Kernel 1: per-batch bitonic sort of the 1024 X values (bias hardcoded at
// slot 0 since bias=1.0 <= min X; tie order provably irrelevant). Strides <=16
// in registers via shfl_xor; strides >=32 via shared memory.
// ---------------------------------------------------------------------------
__global__ void __launch_bounds__(1024) snn_sort_kernel(const float* __restrict__ X) {
    __shared__ unsigned long long sh[1024];
    __shared__ float sx[1025];
    const int b = blockIdx.x;
    const int t = threadIdx.x;

    unsigned long long v =
        ((unsigned long long)__float_as_uint(X[b * INSZ + t]) << 32) | (unsigned)t;

    #pragma unroll 1
    for (int size = 2; size <= 1024; size <<= 1) {
        #pragma unroll 1
        for (int stride = size >> 1; stride >= 32; stride >>= 1) {
            sh[t] = v;
            __syncthreads();
            const unsigned long long u = sh[t ^ stride];
            __syncthreads();
            const bool dir = (t & size) != 0;
            const bool keepmin = (((t & stride) == 0) != dir);
            v = keepmin ? (v < u ? v : u) : (v < u ? u : v);
        }
        const int s0 = (size >> 1) < 16 ? (size >> 1) : 16;
        #pragma unroll 1
        for (int stride = s0; stride >= 1; stride >>= 1) {
            const unsigned long long u = __shfl_xor_sync(0xffffffffu, v, stride);
            const bool dir = (t & size) != 0;
            const bool keepmin = (((t & stride) == 0) != dir);
            v = keepmin ? (v < u ? v : u) : (v < u ? u : v);
        }
    }

    sx[t + 1] = __uint_as_float((unsigned)(v >> 32));
    if (t == 0) sx[0] = 1.0f;
    __syncthreads();

    const int row = (int)(v & 0xffffffffu);
    const int s = t + 1;
    const float x  = sx[s];
    const float xn = (s == KSZ - 1) ? MAX_SPIKE : sx[s + 1];
    g_xs[b][s]  = x;
    g_dx[b][s]  = xn - x;
    g_row[b][s] = row * (MSZ * 4);
    if (t == 0) {
        g_xs[b][0]  = 1.0f;
        g_dx[b][0]  = sx[1] - 1.0f;
        g_row[b][0] = INSZ * (MSZ * 4);
    }
    if (t < KPAD - KSZ) {   // padding: w-row = bias row (all zeros), dx = 0 -> no-op
        g_xs[b][KSZ + t]  = MAX_SPIKE;
        g_dx[b][KSZ + t]  = 0.0f;
        g_row[b][KSZ + t] = INSZ * (MSZ * 4);
    }
}

// ---------------------------------------------------------------------------
// Kernel 2: margin-recurrence scan with a cp.async staging pipeline.
//   cwp_k = cw_k - 1;  G_{k+1} = G_k + cwp_k * dx_k   (G_0 = -x_0 = -1)
// First k with G_{k+1} >= 0 is the unique first valid window:
//   T = x_k - G_k / cwp_k.
// W rows are staged into smem 16 rows (8KB) at a time, 4 stages, 3 in flight,
// so every weight read in the consume loop is a guaranteed smem hit.
// Grid: (MSZ/128, BATCH), 128 threads, 1 output column per thread.
// ---------------------------------------------------------------------------
__global__ void __launch_bounds__(128) snn_scan_kernel(
    const float* __restrict__ W, float* __restrict__ out)
{
    __shared__ float sbuf[NSTAGE][CHUNK * 128];   // 32 KB
    __shared__ float s_dx[KPAD];
    __shared__ int   s_row[KPAD];

    const int b = blockIdx.y;
    const int t = threadIdx.x;
    const int mblock = blockIdx.x * 128;
    const char* Wcol = (const char*)W + (size_t)mblock * 4;

    for (int i = t; i < KPAD; i += 128) {
        s_dx[i]  = g_dx[b][i];
        s_row[i] = g_row[b][i];
    }
    __syncthreads();

    // issue one chunk: 16 rows x 512B = 8KB, 4 x 16B cp.async per thread
    auto issue_chunk = [&](int c) {
        const int kb = c * CHUNK;
        float* dstbase = sbuf[c & (NSTAGE - 1)];
        #pragma unroll
        for (int i = 0; i < 4; i++) {
            const int lin = i * 128 + t;
            const int r   = lin >> 5;          // row within chunk (0..15)
            const int seg = lin & 31;          // 16B segment within 512B row slice
            const char* src = Wcol + s_row[kb + r] + seg * 16;
            unsigned dsts = (unsigned)__cvta_generic_to_shared(dstbase + r * 128 + seg * 4);
            asm volatile("cp.async.cg.shared.global [%0], [%1], 16;\n"
                         :: "r"(dsts), "l"(src));
        }
        asm volatile("cp.async.commit_group;\n");
    };

    issue_chunk(0);
    issue_chunk(1);
    issue_chunk(2);

    float cwp = -1.0f;          // cw - THRESHOLD
    float G   = -1.0f;          // G_0 = -x_0, x_0 = bias = 1.0
    float Gf  = 0.0f, cf = 1.0f;
    int   kf  = 0;
    bool  nd  = true;           // not done

    #pragma unroll 1
    for (int c = 0; c < NCHUNK; c++) {
        asm volatile("cp.async.wait_group 2;\n");
        __syncthreads();
        const float* buf = sbuf[c & (NSTAGE - 1)];
        const int kb = c * CHUNK;
        #pragma unroll
        for (int u = 0; u < CHUNK; u++) {
            const float w  = buf[u * 128 + t];
            const float dx = s_dx[kb + u];
            cwp += w;
            const float Gn = fmaf(cwp, dx, G);
            Gf = nd ? G       : Gf;
            cf = nd ? cwp     : cf;
            kf = nd ? (kb + u) : kf;
            nd = nd && (Gn < 0.0f);
            G  = Gn;
        }
        if (c + 3 < NCHUNK) issue_chunk(c + 3);
        else asm volatile("cp.async.commit_group;\n");   // empty group keeps count
    }

    out[(size_t)b * MSZ + mblock + t] = nd ? MAX_SPIKE : (g_xs[b][kf] - Gf / cf);
}

// ---------------------------------------------------------------------------
extern "C" void kernel_launch(void* const* d_in, const int* in_sizes, int n_in,
                              void* d_out, int out_size) {
    const float* X = (const float*)d_in[0];   // [64, 1024] spike times
    const float* W = (const float*)d_in[1];   // [1025, 1024] weights
    float* out = (float*)d_out;               // [64, 1024]

    snn_sort_kernel<<<BATCH, 1024>>>(X);
    snn_scan_kernel<<<dim3(MSZ / 128, BATCH), 128>>>(W, out);
}